// round 6
// baseline (speedup 1.0000x reference)
#include <cuda_runtime.h>

#define C_DIM   256
#define MAXN    100000
#define EPS_LN  1e-5f

// ---------------------------------------------------------------------------
// Scratch (device globals; no allocation allowed in kernel_launch)
// ---------------------------------------------------------------------------
__device__ float g_cur_u[MAXN * C_DIM];
__device__ float g_cur_i[MAXN * C_DIM];
__device__ float g_H    [MAXN * C_DIM];
__device__ float g_P    [MAXN * C_DIM];
__device__ float g_agg  [MAXN * C_DIM];
__device__ float g_new_u[MAXN * C_DIM];
__device__ float g_new_i[MAXN * C_DIM];
__device__ float g_cnt  [MAXN];

// ---------------------------------------------------------------------------
// GEMM: C[M,N] = op(A[M,K] @ B[K,N] (+bias) (+Cold)) with optional relu.
// 128x128 block, BK=16, 256 threads, 8x8 register micro-tile.
// ---------------------------------------------------------------------------
template<bool RELU, bool ACCUM, bool BIAS>
__global__ __launch_bounds__(256, 2)
void gemm128_kernel(const float* __restrict__ A, const float* __restrict__ B,
                    const float* __restrict__ bias, float* __restrict__ Cout,
                    int M, int K, int N)
{
    __shared__ float As[16][128];   // stored transposed: As[k][m]
    __shared__ float Bs[16][128];   // Bs[k][n]

    const int tid = threadIdx.x;
    const int tx  = tid & 15;       // column group (8 cols each)
    const int ty  = tid >> 4;       // row group (8 rows each)
    const int bx  = blockIdx.x * 128;
    const int by  = blockIdx.y * 128;

    float acc[8][8];
#pragma unroll
    for (int i = 0; i < 8; i++)
#pragma unroll
        for (int j = 0; j < 8; j++) acc[i][j] = 0.f;

    for (int k0 = 0; k0 < K; k0 += 16) {
        // Load A tile [128 x 16] -> transposed smem
#pragma unroll
        for (int i = 0; i < 2; i++) {
            int idx = tid + i * 256;        // 0..511 float4 slots
            int r   = idx >> 2;             // 0..127 row in tile
            int c4  = (idx & 3) << 2;       // 0,4,8,12
            int grow = by + r;
            float4 v = make_float4(0.f, 0.f, 0.f, 0.f);
            if (grow < M)
                v = *(const float4*)(A + (size_t)grow * K + k0 + c4);
            As[c4 + 0][r] = v.x;
            As[c4 + 1][r] = v.y;
            As[c4 + 2][r] = v.z;
            As[c4 + 3][r] = v.w;
        }
        // Load B tile [16 x 128]
#pragma unroll
        for (int i = 0; i < 2; i++) {
            int idx = tid + i * 256;
            int r   = idx >> 5;             // 0..15
            int cc  = (idx & 31) << 2;      // 0..124
            *(float4*)(&Bs[r][cc]) =
                *(const float4*)(B + (size_t)(k0 + r) * N + bx + cc);
        }
        __syncthreads();

#pragma unroll
        for (int kk = 0; kk < 16; kk++) {
            float4 a0 = *(const float4*)(&As[kk][ty * 8]);
            float4 a1 = *(const float4*)(&As[kk][ty * 8 + 4]);
            float4 b0 = *(const float4*)(&Bs[kk][tx * 8]);
            float4 b1 = *(const float4*)(&Bs[kk][tx * 8 + 4]);
            float a[8] = {a0.x, a0.y, a0.z, a0.w, a1.x, a1.y, a1.z, a1.w};
            float b[8] = {b0.x, b0.y, b0.z, b0.w, b1.x, b1.y, b1.z, b1.w};
#pragma unroll
            for (int i = 0; i < 8; i++)
#pragma unroll
                for (int j = 0; j < 8; j++)
                    acc[i][j] = fmaf(a[i], b[j], acc[i][j]);
        }
        __syncthreads();
    }

    // Epilogue
    float4 bv0 = make_float4(0.f, 0.f, 0.f, 0.f);
    float4 bv1 = make_float4(0.f, 0.f, 0.f, 0.f);
    if (BIAS) {
        bv0 = *(const float4*)(bias + bx + tx * 8);
        bv1 = *(const float4*)(bias + bx + tx * 8 + 4);
    }
#pragma unroll
    for (int i = 0; i < 8; i++) {
        int row = by + ty * 8 + i;
        if (row >= M) break;
        float* crow = Cout + (size_t)row * N + bx + tx * 8;
#pragma unroll
        for (int jj = 0; jj < 2; jj++) {
            float4 v = make_float4(acc[i][jj * 4 + 0], acc[i][jj * 4 + 1],
                                   acc[i][jj * 4 + 2], acc[i][jj * 4 + 3]);
            if (BIAS) {
                float4 bb = jj ? bv1 : bv0;
                v.x += bb.x; v.y += bb.y; v.z += bb.z; v.w += bb.w;
            }
            if (ACCUM) {
                float4 ov = *(const float4*)(crow + jj * 4);
                v.x += ov.x; v.y += ov.y; v.z += ov.z; v.w += ov.w;
            }
            if (RELU) {
                v.x = fmaxf(v.x, 0.f); v.y = fmaxf(v.y, 0.f);
                v.z = fmaxf(v.z, 0.f); v.w = fmaxf(v.w, 0.f);
            }
            *(float4*)(crow + jj * 4) = v;
        }
    }
}

// ---------------------------------------------------------------------------
// Warp reduce
// ---------------------------------------------------------------------------
__device__ __forceinline__ float warp_sum(float v)
{
#pragma unroll
    for (int o = 16; o > 0; o >>= 1)
        v += __shfl_xor_sync(0xffffffffu, v, o);
    return v;
}

// ---------------------------------------------------------------------------
// Edge stage: one warp per edge.
//   msg = LN(x_src[src] - P[dst]) * g + b
//   agg[dst] += msg (vector red), cnt[dst] += 1
// ---------------------------------------------------------------------------
__global__ void edge_msg_kernel(const float* __restrict__ xsrc,
                                const float* __restrict__ Pn,
                                const int*   __restrict__ ei,
                                const float* __restrict__ gg,
                                const float* __restrict__ bb,
                                float* __restrict__ agg,
                                float* __restrict__ cnt,
                                int nE)
{
    int w    = (blockIdx.x * blockDim.x + threadIdx.x) >> 5;
    int lane = threadIdx.x & 31;
    if (w >= nE) return;

    int s = __ldg(ei + w);
    int d = __ldg(ei + nE + w);
    int c0 = lane << 3;

    const float4* xs = (const float4*)(xsrc + (size_t)s * C_DIM + c0);
    const float4* pp = (const float4*)(Pn   + (size_t)d * C_DIM + c0);
    float4 a0 = xs[0], a1 = xs[1];
    float4 p0 = pp[0], p1 = pp[1];
    float r[8] = {a0.x - p0.x, a0.y - p0.y, a0.z - p0.z, a0.w - p0.w,
                  a1.x - p1.x, a1.y - p1.y, a1.z - p1.z, a1.w - p1.w};

    float s1 = 0.f;
#pragma unroll
    for (int i = 0; i < 8; i++) s1 += r[i];
    s1 = warp_sum(s1);
    float mean = s1 * (1.f / 256.f);

    float s2 = 0.f;
#pragma unroll
    for (int i = 0; i < 8; i++) { float t = r[i] - mean; s2 += t * t; }
    s2 = warp_sum(s2);
    float inv = rsqrtf(s2 * (1.f / 256.f) + EPS_LN);

    float4 g0 = *(const float4*)(gg + c0);
    float4 g1 = *(const float4*)(gg + c0 + 4);
    float4 e0 = *(const float4*)(bb + c0);
    float4 e1 = *(const float4*)(bb + c0 + 4);

    float m[8];
    m[0] = (r[0] - mean) * inv * g0.x + e0.x;
    m[1] = (r[1] - mean) * inv * g0.y + e0.y;
    m[2] = (r[2] - mean) * inv * g0.z + e0.z;
    m[3] = (r[3] - mean) * inv * g0.w + e0.w;
    m[4] = (r[4] - mean) * inv * g1.x + e1.x;
    m[5] = (r[5] - mean) * inv * g1.y + e1.y;
    m[6] = (r[6] - mean) * inv * g1.z + e1.z;
    m[7] = (r[7] - mean) * inv * g1.w + e1.w;

    float* dstp = agg + (size_t)d * C_DIM + c0;
    asm volatile("red.global.add.v4.f32 [%0], {%1,%2,%3,%4};"
                 :: "l"(dstp), "f"(m[0]), "f"(m[1]), "f"(m[2]), "f"(m[3])
                 : "memory");
    asm volatile("red.global.add.v4.f32 [%0], {%1,%2,%3,%4};"
                 :: "l"(dstp + 4), "f"(m[4]), "f"(m[5]), "f"(m[6]), "f"(m[7])
                 : "memory");
    if (lane == 0) atomicAdd(cnt + d, 1.0f);
}

// ---------------------------------------------------------------------------
// agg[i] /= max(cnt[i], 1)
// ---------------------------------------------------------------------------
__global__ void norm_agg_kernel(float* __restrict__ agg,
                                const float* __restrict__ cnt, int n)
{
    int idx = blockIdx.x * blockDim.x + threadIdx.x;   // one float4 each
    int total = n * (C_DIM / 4);
    if (idx >= total) return;
    int row = idx / (C_DIM / 4);
    float inv = 1.f / fmaxf(__ldg(cnt + row), 1.f);
    float4* p = ((float4*)agg) + idx;
    float4 v = *p;
    v.x *= inv; v.y *= inv; v.z *= inv; v.w *= inv;
    *p = v;
}

// ---------------------------------------------------------------------------
// out = relu(LN(X) * g + b), one warp per row
// ---------------------------------------------------------------------------
__global__ void node_ln_relu_kernel(const float* __restrict__ X,
                                    const float* __restrict__ gg,
                                    const float* __restrict__ bb,
                                    float* __restrict__ out, int M)
{
    int w    = (blockIdx.x * blockDim.x + threadIdx.x) >> 5;
    int lane = threadIdx.x & 31;
    if (w >= M) return;
    int c0 = lane << 3;

    const float4* xp = (const float4*)(X + (size_t)w * C_DIM + c0);
    float4 a0 = xp[0], a1 = xp[1];
    float r[8] = {a0.x, a0.y, a0.z, a0.w, a1.x, a1.y, a1.z, a1.w};

    float s1 = 0.f;
#pragma unroll
    for (int i = 0; i < 8; i++) s1 += r[i];
    s1 = warp_sum(s1);
    float mean = s1 * (1.f / 256.f);

    float s2 = 0.f;
#pragma unroll
    for (int i = 0; i < 8; i++) { float t = r[i] - mean; s2 += t * t; }
    s2 = warp_sum(s2);
    float inv = rsqrtf(s2 * (1.f / 256.f) + EPS_LN);

    float4 g0 = *(const float4*)(gg + c0);
    float4 g1 = *(const float4*)(gg + c0 + 4);
    float4 e0 = *(const float4*)(bb + c0);
    float4 e1 = *(const float4*)(bb + c0 + 4);

    float4 o0, o1;
    o0.x = fmaxf((r[0] - mean) * inv * g0.x + e0.x, 0.f);
    o0.y = fmaxf((r[1] - mean) * inv * g0.y + e0.y, 0.f);
    o0.z = fmaxf((r[2] - mean) * inv * g0.z + e0.z, 0.f);
    o0.w = fmaxf((r[3] - mean) * inv * g0.w + e0.w, 0.f);
    o1.x = fmaxf((r[4] - mean) * inv * g1.x + e1.x, 0.f);
    o1.y = fmaxf((r[5] - mean) * inv * g1.y + e1.y, 0.f);
    o1.z = fmaxf((r[6] - mean) * inv * g1.z + e1.z, 0.f);
    o1.w = fmaxf((r[7] - mean) * inv * g1.w + e1.w, 0.f);

    float4* op = (float4*)(out + (size_t)w * C_DIM + c0);
    op[0] = o0;
    op[1] = o1;
}

// ---------------------------------------------------------------------------
// Host-side conv driver (all launches on default stream, graph-capturable)
// ---------------------------------------------------------------------------
static void launch_conv(const float* xsrc, const float* xdst, int n_dst,
                        const int* ei, int nE,
                        const float* w1, const float* b1,
                        const float* w2, const float* b2,
                        const float* mg, const float* mb,
                        const float* lw, const float* lb,
                        float* Hbuf, float* Pbuf, float* aggbuf, float* cntbuf,
                        float* outbuf)
{
    dim3 blk(256);
    dim3 grd(C_DIM / 128, (n_dst + 127) / 128);

    // P = relu(xdst @ W1 + b1) @ W2 + b2   (per destination node, not per edge)
    gemm128_kernel<true,  false, true ><<<grd, blk>>>(xdst, w1, b1, Hbuf, n_dst, C_DIM, C_DIM);
    gemm128_kernel<false, false, true ><<<grd, blk>>>(Hbuf, w2, b2, Pbuf, n_dst, C_DIM, C_DIM);

    cudaMemsetAsync(aggbuf, 0, (size_t)n_dst * C_DIM * sizeof(float));
    cudaMemsetAsync(cntbuf, 0, (size_t)n_dst * sizeof(float));

    int eb = (nE * 32 + 255) / 256;
    edge_msg_kernel<<<eb, 256>>>(xsrc, Pbuf, ei, mg, mb, aggbuf, cntbuf, nE);

    int nb = (n_dst * (C_DIM / 4) + 255) / 256;
    norm_agg_kernel<<<nb, 256>>>(aggbuf, cntbuf, n_dst);

    // out = xdst @ Wx + aggn @ Wa + lb   (split of concat GEMM)
    gemm128_kernel<false, false, true ><<<grd, blk>>>(xdst,   lw,                 lb,      outbuf, n_dst, C_DIM, C_DIM);
    gemm128_kernel<false, true,  false><<<grd, blk>>>(aggbuf, lw + C_DIM * C_DIM, nullptr, outbuf, n_dst, C_DIM, C_DIM);
}

extern "C" void kernel_launch(void* const* d_in, const int* in_sizes, int n_in,
                              void* d_out, int out_size)
{
    const float* x_user = (const float*)d_in[0];
    const float* x_item = (const float*)d_in[1];
    const float* pw1    = (const float*)d_in[2];
    const float* pb1    = (const float*)d_in[3];
    const float* pw2    = (const float*)d_in[4];
    const float* pb2    = (const float*)d_in[5];
    const float* msg_g  = (const float*)d_in[6];
    const float* msg_b  = (const float*)d_in[7];
    const float* lin_w  = (const float*)d_in[8];
    const float* lin_b  = (const float*)d_in[9];
    const float* node_g = (const float*)d_in[10];
    const float* node_b = (const float*)d_in[11];
    const int*   ei_ui  = (const int*)d_in[12];
    const int*   ei_iu  = (const int*)d_in[13];

    const int NUn = in_sizes[0] / C_DIM;
    const int NIn = in_sizes[1] / C_DIM;
    const int nE0 = in_sizes[12] / 2;   // user->item edges
    const int nE1 = in_sizes[13] / 2;   // item->user edges
    const int Lm  = 2;

    float *cur_u, *cur_i, *Hb, *Pb, *aggb, *cntb, *new_u, *new_i;
    cudaGetSymbolAddress((void**)&cur_u, g_cur_u);
    cudaGetSymbolAddress((void**)&cur_i, g_cur_i);
    cudaGetSymbolAddress((void**)&Hb,    g_H);
    cudaGetSymbolAddress((void**)&Pb,    g_P);
    cudaGetSymbolAddress((void**)&aggb,  g_agg);
    cudaGetSymbolAddress((void**)&cntb,  g_cnt);
    cudaGetSymbolAddress((void**)&new_u, g_new_u);
    cudaGetSymbolAddress((void**)&new_i, g_new_i);

    cudaMemcpyAsync(cur_u, x_user, (size_t)NUn * C_DIM * sizeof(float),
                    cudaMemcpyDeviceToDevice);
    cudaMemcpyAsync(cur_i, x_item, (size_t)NIn * C_DIM * sizeof(float),
                    cudaMemcpyDeviceToDevice);

    float* out_f = (float*)d_out;

    for (int l = 0; l < Lm; l++) {
        // edge type 0: user -> item (dst = item), params [l,0]
        {
            int t = l * 2 + 0;
            launch_conv(cur_u, cur_i, NIn, ei_ui, nE0,
                        pw1 + (size_t)t * C_DIM * C_DIM, pb1 + (size_t)t * C_DIM,
                        pw2 + (size_t)t * C_DIM * C_DIM, pb2 + (size_t)t * C_DIM,
                        msg_g + (size_t)t * C_DIM, msg_b + (size_t)t * C_DIM,
                        lin_w + (size_t)t * 2 * C_DIM * C_DIM, lin_b + (size_t)t * C_DIM,
                        Hb, Pb, aggb, cntb, new_i);
        }
        // edge type 1: item -> user (dst = user), params [l,1]
        {
            int t = l * 2 + 1;
            launch_conv(cur_i, cur_u, NUn, ei_iu, nE1,
                        pw1 + (size_t)t * C_DIM * C_DIM, pb1 + (size_t)t * C_DIM,
                        pw2 + (size_t)t * C_DIM * C_DIM, pb2 + (size_t)t * C_DIM,
                        msg_g + (size_t)t * C_DIM, msg_b + (size_t)t * C_DIM,
                        lin_w + (size_t)t * 2 * C_DIM * C_DIM, lin_b + (size_t)t * C_DIM,
                        Hb, Pb, aggb, cntb, new_u);
        }

        float* dst_u = (l == Lm - 1) ? out_f : cur_u;
        float* dst_i = (l == Lm - 1) ? (out_f + (size_t)NUn * C_DIM) : cur_i;

        // node-type LN + relu: node_type 0 = user, 1 = item
        int ub = (NUn * 32 + 255) / 256;
        int ib = (NIn * 32 + 255) / 256;
        node_ln_relu_kernel<<<ub, 256>>>(new_u,
                                         node_g + (size_t)(l * 2 + 0) * C_DIM,
                                         node_b + (size_t)(l * 2 + 0) * C_DIM,
                                         dst_u, NUn);
        node_ln_relu_kernel<<<ib, 256>>>(new_i,
                                         node_g + (size_t)(l * 2 + 1) * C_DIM,
                                         node_b + (size_t)(l * 2 + 1) * C_DIM,
                                         dst_i, NIn);
    }
    (void)n_in; (void)out_size;
}